// round 11
// baseline (speedup 1.0000x reference)
#include <cuda_runtime.h>
#include <cuda_bf16.h>
#include <cstdint>

#define NB 32
#define NCh 128
#define NHW 16
#define NV 8192
#define NELEM (NB*NCh*NHW*NHW)   // 1048576
#define NPOS  (NB*NHW*NHW)       // 8192
// smem: [0,1024) hesq x2 | [1024,9216) merge buf | [16384,+64K) A | [81920,+32K)x2 B
#define GEMM_SMEM 147456

// ---------------- persistent device scratch ----------------
__device__ float g_frest[NELEM];              // NHWC (also pn=16 query matrix)
__device__ float g_fhat[NELEM];
__device__ float g_f0[NELEM];
__device__ float g_rest[NPOS*NCh];            // [N][128] pooled queries
__device__ float g_h[NELEM];
__device__ float g_half_esq[NV];
__device__ __nv_bfloat16 gB[NV*128];          // codebook hi-part
__device__ float g_t1s[NPOS*64];  __device__ int g_t1i[NPOS*64];
__device__ float g_t2s[NPOS*64];  __device__ int g_t2i[NPOS*64];
__device__ int   g_idx[NPOS];
__device__ int   g_flagcnt;
__device__ int   g_flaglist[NPOS];
__device__ float g_wT2[4*9*64*256];           // conv weights [k][tap][ci2][co*2+p]
__device__ float g_Wall[5*16*16];
__device__ float g_sse[8];
__device__ int   g_swap;

// ---------------- f32x2 helpers (conv path) ----------------
__device__ __forceinline__ void f2_unpack(unsigned long long v, float& x, float& y) {
    asm("mov.b64 {%0, %1}, %2;" : "=f"(x), "=f"(y) : "l"(v));
}
__device__ __forceinline__ void ffma2_ip(unsigned long long& c,
                                         unsigned long long a, unsigned long long b) {
    asm("fma.rn.f32x2 %0, %1, %2, %0;" : "+l"(c) : "l"(a), "l"(b));
}

// ---------------- mma / cp.async helpers ----------------
__device__ __forceinline__ uint32_t smem_u32(const void* p) {
    uint32_t a;
    asm("{ .reg .u64 t; cvta.to.shared.u64 t, %1; cvt.u32.u64 %0, t; }" : "=r"(a) : "l"(p));
    return a;
}
__device__ __forceinline__ void ldsm_x4(uint32_t& r0, uint32_t& r1, uint32_t& r2,
                                        uint32_t& r3, uint32_t addr) {
    asm volatile("ldmatrix.sync.aligned.m8n8.x4.shared.b16 {%0,%1,%2,%3}, [%4];"
        : "=r"(r0), "=r"(r1), "=r"(r2), "=r"(r3) : "r"(addr));
}
__device__ __forceinline__ void mma16816(float* d, const uint32_t* a, const uint32_t* b) {
    asm volatile("mma.sync.aligned.m16n8k16.row.col.f32.bf16.bf16.f32 "
        "{%0,%1,%2,%3}, {%4,%5,%6,%7}, {%8,%9}, {%0,%1,%2,%3};"
        : "+f"(d[0]), "+f"(d[1]), "+f"(d[2]), "+f"(d[3])
        : "r"(a[0]), "r"(a[1]), "r"(a[2]), "r"(a[3]), "r"(b[0]), "r"(b[1]));
}
__device__ __forceinline__ void cp16(uint32_t dst, const void* src) {
    asm volatile("cp.async.cg.shared.global [%0], [%1], 16;" :: "r"(dst), "l"(src));
}
__device__ __forceinline__ void cp_commit() {
    asm volatile("cp.async.commit_group;" ::: "memory");
}
template<int Nn> __device__ __forceinline__ void cp_wait() {
    asm volatile("cp.async.wait_group %0;" :: "n"(Nn) : "memory");
}
__device__ __forceinline__ void top2_merge(float& s1, int& i1, float& s2, int& i2,
                                           float os1, int oi1, float os2, int oi2) {
    if (os1 > s1 || (os1 == s1 && oi1 < i1)) {
        float ns2; int ni2;
        if (s1 > os2 || (s1 == os2 && i1 < oi2)) { ns2 = s1; ni2 = i1; }
        else { ns2 = os2; ni2 = oi2; }
        s1 = os1; i1 = oi1; s2 = ns2; i2 = ni2;
    } else {
        if (os1 > s2 || (os1 == s2 && oi1 < i2)) { s2 = os1; i2 = oi1; }
    }
}

// prefetch one B tile (128 codes x 128 bf16 = 32KB, 256B/row) + hesq via cp.async
__device__ __forceinline__ void prefetch_tile(uint32_t B_u, uint32_t sb, int bsel,
                                              int v0, int tid) {
    uint32_t Bb = B_u + (uint32_t)bsel*32768u;
    #pragma unroll
    for (int q = 0; q < 4; q++) {
        int idx  = q*512 + tid;
        int code = idx >> 4, c = idx & 15;
        cp16(Bb + (uint32_t)(code*256 + ((c ^ (code & 7)) << 4)),
             gB + (size_t)(v0 + code)*128 + c*8);
    }
    if (tid < 32) cp16(sb + (uint32_t)(bsel*512 + tid*16), g_half_esq + v0 + tid*4);
    cp_commit();
}

// ---------------- input disambiguation ----------------
__global__ void k_detect(const float* __restrict__ a) {
    __shared__ float red[256];
    int t = threadIdx.x;
    float s = 0.f;
    #pragma unroll 4
    for (int k = 0; k < 64; k++) { float x = a[t + 256*k]; s += x*x; }
    red[t] = s; __syncthreads();
    for (int m = 128; m > 0; m >>= 1) { if (t < m) red[t] += red[t+m]; __syncthreads(); }
    if (t == 0) g_swap = (red[0] > 0.5f * 16384.f) ? 0 : 1;
}

__device__ __forceinline__ double keys_cubic(double x) {
    x = fabs(x);
    if (x < 1.0) return ((1.5*x - 2.5)*x)*x + 1.0;
    if (x < 2.0) return ((-0.5*x + 2.5)*x - 4.0)*x + 2.0;
    return 0.0;
}

// ---------------- merged init (grid-partitioned) ----------------
__global__ void k_init_all(const float* __restrict__ a, const float* __restrict__ b,
                           const float* __restrict__ phi_w) {
    int blk = blockIdx.x;
    int t = threadIdx.x;
    if (blk < 4096) {
        const float* f = g_swap ? b : a;
        int i = blk*256 + t;
        if (i < 8) g_sse[i] = 0.f;
        int bb = i >> 15;
        int c  = (i >> 8) & 127;
        int yx = i & 255;
        int nh = ((((bb << 8) | yx) << 7) | c);
        float v = f[i];
        g_frest[nh] = v;
        g_f0[nh]    = v;
        g_fhat[nh]  = 0.f;
    } else if (blk < 8192) {
        const float* emb = g_swap ? a : b;
        int v0 = (blk - 4096)*2;
        int v = v0 + (t >> 7);
        int c = t & 127;
        float x = emb[v*NCh + c];
        gB[(size_t)v*128 + c] = __float2bfloat16(x);
        float s = x*x;
        #pragma unroll
        for (int m = 16; m > 0; m >>= 1) s += __shfl_xor_sync(0xffffffffu, s, m);
        __shared__ float ws[8];
        if ((t & 31) == 0) ws[t >> 5] = s;
        __syncthreads();
        if (t == 0)   g_half_esq[v0]   = 0.5f*(ws[0]+ws[1]+ws[2]+ws[3]);
        if (t == 128) g_half_esq[v0+1] = 0.5f*(ws[4]+ws[5]+ws[6]+ws[7]);
    } else if (blk < 10496) {
        int o = (blk - 8192)*256 + t;
        int co2 = o & 255;
        int p  = co2 & 1;
        int co = co2 >> 1;
        int r  = o >> 8;
        int ci2 = r & 63; r >>= 6;
        int t9 = r % 9;
        int k  = r / 9;
        int ky = t9 / 3, kx = t9 % 3;
        int ci = ci2*2 + p;
        g_wT2[o] = phi_w[(((k*NCh + co)*NCh + ci)*3 + ky)*3 + kx];
    } else {
        if (t >= 80) return;
        const int pns[5] = {1,2,4,8,16};
        int si = t >> 4, i = t & 15;
        int pn = pns[si];
        double sample = (i + 0.5) * (double)pn / 16.0 - 0.5;
        double w[16]; double tot = 0.0;
        for (int j = 0; j < 16; j++) w[j] = 0.0;
        for (int j = 0; j < pn; j++) { w[j] = keys_cubic(sample - (double)j); tot += w[j]; }
        for (int j = 0; j < 16; j++) g_Wall[(si*16 + i)*16 + j] = (float)(w[j] / tot);
    }
}

// ---------------- stage kernels ----------------
__global__ void k_pool(int pn) {
    int n = blockIdx.x;
    int c = threadIdx.x;
    int s = 16 / pn;
    int pp = pn*pn;
    int b   = n / pp;
    int rem = n - b*pp;
    int py = rem / pn, px = rem - py*pn;
    float acc = 0.f;
    int y0 = py*s, x0 = px*s;
    for (int dy = 0; dy < s; dy++)
        for (int dx = 0; dx < s; dx++)
            acc += g_frest[(((b*16 + y0+dy)*16) + (x0+dx))*128 + c];
    g_rest[n*128 + c] = acc / (float)(s*s);
}

// tensor-core NN: 128 rows x 128 codes/tile, K=256 (A=[hi|lo], B=hi wraps),
// cp.async double-buffered B, 512 threads (warps 4m x 4n, each 32x32).
__global__ __launch_bounds__(512, 1) void k_mma(int N, int T, int vsplit, int use_frest) {
    extern __shared__ char smem[];
    uint32_t sb = smem_u32(smem);
    float4* buf = (float4*)(smem + 1024);         // [128 rows][4 wn]
    uint32_t A_u = sb + 16384;
    uint32_t B_u = sb + 81920;
    const float* R = use_frest ? g_frest : g_rest;

    int tid = threadIdx.x;
    int wid = tid >> 5, lane = tid & 31;
    int wm = wid >> 2, wn = wid & 3;
    int rt = blockIdx.x, vslab = blockIdx.y;
    int r0 = rt * 128;
    if (rt == 0 && vslab == 0 && tid == 0) g_flagcnt = 0;

    int vbase = vslab * T * 128;
    prefetch_tile(B_u, sb, 0, vbase, tid);

    // ---- A' prep: 128 rows x 256 bf16 [hi(0..15) | lo(16..31)] chunks, XOR swizzle ----
    {
        int row = tid >> 2, q4 = tid & 3;
        int grow = r0 + row;
        bool valid = grow < N;
        const float4* rp = (const float4*)(R + (size_t)grow*128) + q4*8;
        int xm = row & 7;
        char* Arow = smem + 16384 + row*512;
        #pragma unroll
        for (int p = 0; p < 4; p++) {
            float4 va = valid ? rp[2*p]   : make_float4(0.f,0.f,0.f,0.f);
            float4 vb = valid ? rp[2*p+1] : make_float4(0.f,0.f,0.f,0.f);
            float xs[8] = {va.x,va.y,va.z,va.w,vb.x,vb.y,vb.z,vb.w};
            uint32_t hw[4], lw[4];
            #pragma unroll
            for (int j = 0; j < 4; j++) {
                __nv_bfloat16 h0 = __float2bfloat16(xs[2*j]);
                __nv_bfloat16 h1 = __float2bfloat16(xs[2*j+1]);
                float l0 = xs[2*j]   - __bfloat162float(h0);
                float l1 = xs[2*j+1] - __bfloat162float(h1);
                __nv_bfloat16 g0 = __float2bfloat16(l0);
                __nv_bfloat16 g1 = __float2bfloat16(l1);
                hw[j] = (uint32_t)__bfloat16_as_ushort(h0) |
                        ((uint32_t)__bfloat16_as_ushort(h1) << 16);
                lw[j] = (uint32_t)__bfloat16_as_ushort(g0) |
                        ((uint32_t)__bfloat16_as_ushort(g1) << 16);
            }
            int ch = q4*4 + p;
            int cl = 16 + q4*4 + p;
            *(uint4*)(Arow + ((ch ^ xm) << 4)) = make_uint4(hw[0],hw[1],hw[2],hw[3]);
            *(uint4*)(Arow + ((cl ^ xm) << 4)) = make_uint4(lw[0],lw[1],lw[2],lw[3]);
        }
    }

    float bs1[2][2], bs2[2][2]; int bi1[2][2], bi2[2][2];
    #pragma unroll
    for (int m = 0; m < 2; m++)
        #pragma unroll
        for (int h = 0; h < 2; h++) {
            bs1[m][h] = -3.4e38f; bs2[m][h] = -3.4e38f;
            bi1[m][h] = 0x7fffffff; bi2[m][h] = 0x7fffffff;
        }

    int a_off[2], a_x[2];
    #pragma unroll
    for (int m = 0; m < 2; m++) {
        int arow = wm*32 + m*16 + (lane & 15);
        a_off[m] = arow*512; a_x[m] = arow & 7;
    }
    int ahi = lane >> 4;
    int b_off[2], b_x[2];
    #pragma unroll
    for (int nb = 0; nb < 2; nb++) {
        int brow = wn*32 + nb*16 + ((lane >> 4) << 3) + (lane & 7);
        b_off[nb] = brow*256; b_x[nb] = brow & 7;
    }
    int bhi = (lane >> 3) & 1;

    for (int t = 0; t < T; t++) {
        if (t + 1 < T) prefetch_tile(B_u, sb, (t+1) & 1, vbase + (t+1)*128, tid);
        if (t + 1 < T) cp_wait<1>(); else cp_wait<0>();
        __syncthreads();

        uint32_t Bb = B_u + (uint32_t)((t & 1)*32768);
        const float* hs = (const float*)(smem + (t & 1)*512);
        int v0 = vbase + t*128;

        float acc[2][4][4];
        #pragma unroll
        for (int m = 0; m < 2; m++)
            #pragma unroll
            for (int n = 0; n < 4; n++)
                #pragma unroll
                for (int j = 0; j < 4; j++) acc[m][n][j] = 0.f;

        #pragma unroll 4
        for (int ks = 0; ks < 16; ks++) {
            uint32_t af[2][4];
            #pragma unroll
            for (int m = 0; m < 2; m++) {
                uint32_t addr = A_u + a_off[m] + (uint32_t)(((ks*2 + ahi) ^ a_x[m]) << 4);
                ldsm_x4(af[m][0], af[m][1], af[m][2], af[m][3], addr);
            }
            uint32_t bfr[2][4];
            #pragma unroll
            for (int nb = 0; nb < 2; nb++) {
                int chunk = (ks*2 + bhi) & 15;     // B wraps: lo ksteps reuse hi codebook
                uint32_t addr = Bb + b_off[nb] + (uint32_t)((chunk ^ b_x[nb]) << 4);
                ldsm_x4(bfr[nb][0], bfr[nb][1], bfr[nb][2], bfr[nb][3], addr);
            }
            #pragma unroll
            for (int m = 0; m < 2; m++)
                #pragma unroll
                for (int n = 0; n < 4; n++)
                    mma16816(acc[m][n], af[m], &bfr[n >> 1][(n & 1)*2]);
        }

        #pragma unroll
        for (int m = 0; m < 2; m++)
            #pragma unroll
            for (int h = 0; h < 2; h++) {
                float s1 = bs1[m][h], s2 = bs2[m][h];
                int   i1 = bi1[m][h], i2 = bi2[m][h];
                #pragma unroll
                for (int n = 0; n < 4; n++) {
                    int cc = wn*32 + n*8 + (lane & 3)*2;
                    #pragma unroll
                    for (int j = 0; j < 2; j++) {
                        float s = acc[m][n][h*2 + j] - hs[cc + j];
                        int code = v0 + cc + j;
                        if (s > s1) { s2 = s1; i2 = i1; s1 = s; i1 = code; }
                        else if (s > s2) { s2 = s; i2 = code; }
                    }
                }
                bs1[m][h] = s1; bs2[m][h] = s2; bi1[m][h] = i1; bi2[m][h] = i2;
            }
        __syncthreads();
    }

    // quad-lane merge (lanes with same lane>>2 cover same rows)
    #pragma unroll
    for (int m = 0; m < 2; m++)
        #pragma unroll
        for (int h = 0; h < 2; h++) {
            float s1 = bs1[m][h], s2 = bs2[m][h];
            int   i1 = bi1[m][h], i2 = bi2[m][h];
            #pragma unroll
            for (int d = 1; d <= 2; d <<= 1) {
                float os1 = __shfl_xor_sync(0xffffffffu, s1, d);
                int   oi1 = __shfl_xor_sync(0xffffffffu, i1, d);
                float os2 = __shfl_xor_sync(0xffffffffu, s2, d);
                int   oi2 = __shfl_xor_sync(0xffffffffu, i2, d);
                top2_merge(s1, i1, s2, i2, os1, oi1, os2, oi2);
            }
            if ((lane & 3) == 0) {
                int row = wm*32 + m*16 + h*8 + (lane >> 2);
                buf[row*4 + wn] = make_float4(s1, __int_as_float(i1),
                                              s2, __int_as_float(i2));
            }
        }
    __syncthreads();

    if (tid < 128) {
        float4 p = buf[tid*4];
        float s1 = p.x, s2 = p.z; int i1 = __float_as_int(p.y), i2 = __float_as_int(p.w);
        #pragma unroll
        for (int w = 1; w < 4; w++) {
            float4 q = buf[tid*4 + w];
            top2_merge(s1, i1, s2, i2, q.x, __float_as_int(q.y), q.z, __float_as_int(q.w));
        }
        int grow = r0 + tid;
        if (grow < N) {
            int o = grow*vsplit + vslab;
            g_t1s[o] = s1; g_t1i[o] = i1;
            g_t2s[o] = s2; g_t2i[o] = i2;
        }
    }
}

// merge per-slab top-2; flag ambiguous rows
__global__ void k_merge(int N, int vsplit, int use_frest) {
    int r = blockIdx.x*256 + threadIdx.x;
    if (r >= N) return;
    int o0 = r*vsplit;
    float s1 = g_t1s[o0], s2 = g_t2s[o0];
    int   i1 = g_t1i[o0], i2 = g_t2i[o0];
    for (int sl = 1; sl < vsplit; sl++) {
        int o = o0 + sl;
        top2_merge(s1, i1, s2, i2, g_t1s[o], g_t1i[o], g_t2s[o], g_t2i[o]);
    }
    const float* R = use_frest ? g_frest : g_rest;
    const float4* rp = (const float4*)(R + (size_t)r*128);
    float nr = 0.f;
    #pragma unroll 8
    for (int q = 0; q < 32; q++) {
        float4 v = rp[q];
        nr += v.x*v.x + v.y*v.y + v.z*v.z + v.w*v.w;
    }
    float eps = 4e-3f * sqrtf(nr) + 1e-3f;   // >=13 sigma of r.lo(e) error
    g_idx[r] = i1;
    if (s1 - s2 <= eps) {
        int p = atomicAdd(&g_flagcnt, 1);
        g_flaglist[p] = r;
    }
}

// exact fp32 full scan for flagged rows
__global__ void k_exact(const float* __restrict__ a_, const float* __restrict__ b_,
                        int use_frest) {
    const float* emb = g_swap ? a_ : b_;
    const float* R = use_frest ? g_frest : g_rest;
    __shared__ float rs[128];
    __shared__ float wss[8]; __shared__ int wsi[8];
    int tid = threadIdx.x;
    int nflag = g_flagcnt;
    for (int li = blockIdx.x; li < nflag; li += gridDim.x) {
        int r = g_flaglist[li];
        if (tid < 128) rs[tid] = R[(size_t)r*128 + tid];
        __syncthreads();
        float bs = -3.4e38f; int bi = 0x7fffffff;
        for (int v = tid; v < NV; v += 256) {
            const float4* ep = (const float4*)(emb + (size_t)v*128);
            float a0=0.f,a1=0.f,a2=0.f,a3=0.f;
            #pragma unroll 8
            for (int q = 0; q < 32; q++) {
                float4 e = ep[q];
                a0 = fmaf(rs[q*4],   e.x, a0);
                a1 = fmaf(rs[q*4+1], e.y, a1);
                a2 = fmaf(rs[q*4+2], e.z, a2);
                a3 = fmaf(rs[q*4+3], e.w, a3);
            }
            float s = ((a0+a1)+(a2+a3)) - g_half_esq[v];
            if (s > bs || (s == bs && v < bi)) { bs = s; bi = v; }
        }
        #pragma unroll
        for (int m = 16; m >= 1; m >>= 1) {
            float os = __shfl_xor_sync(0xffffffffu, bs, m);
            int   oi = __shfl_xor_sync(0xffffffffu, bi, m);
            if (os > bs || (os == bs && oi < bi)) { bs = os; bi = oi; }
        }
        if ((tid & 31) == 0) { wss[tid>>5] = bs; wsi[tid>>5] = bi; }
        __syncthreads();
        if (tid == 0) {
            for (int w = 1; w < 8; w++) {
                if (wss[w] > bs || (wss[w] == bs && wsi[w] < bi)) { bs = wss[w]; bi = wsi[w]; }
            }
            g_idx[r] = bi;
        }
        __syncthreads();
    }
}

// gather + separable-cubic upsample (pn=16 -> pure gather)
__global__ void k_upsample(const float* __restrict__ a_, const float* __restrict__ b_,
                           int pn, int si) {
    const float* emb = g_swap ? a_ : b_;
    int blk = blockIdx.x;
    int c = threadIdx.x;
    if (pn == 16) {
        g_h[(size_t)blk*128 + c] = emb[(size_t)g_idx[blk]*128 + c];
        return;
    }
    int b = blk >> 8;
    int Y = (blk >> 4) & 15;
    int X = blk & 15;
    const float* Wm = g_Wall + si*256;
    float acc = 0.f;
    for (int py = 0; py < pn; py++) {
        float wy = Wm[Y*16 + py];
        if (wy == 0.f) continue;
        for (int px = 0; px < pn; px++) {
            float wx = Wm[X*16 + px];
            if (wx == 0.f) continue;
            int n = (b*pn + py)*pn + px;
            acc += (wy*wx) * emb[(size_t)g_idx[n]*128 + c];
        }
    }
    g_h[(size_t)blk*128 + c] = acc;
}

// Phi + fused residual update + loss (validated f32x2 path)
__global__ __launch_bounds__(128) void k_conv(const float* __restrict__ bias, int kphi, int si) {
    __shared__ float s_in[3][18][128];
    int y  = blockIdx.x;
    int b  = blockIdx.y;
    int co = threadIdx.x;
    const float* wbase = g_wT2 + (size_t)kphi*(9*64*256);

    #pragma unroll
    for (int ky = 0; ky < 3; ky++) {
        int yy = y + ky - 1;
        #pragma unroll
        for (int xi = 0; xi < 18; xi++) {
            int xx = xi - 1;
            float v = 0.f;
            if (yy >= 0 && yy < 16 && xx >= 0 && xx < 16)
                v = g_h[((b*16+yy)*16+xx)*128 + co];
            s_in[ky][xi][co] = v;
        }
    }
    __syncthreads();

    unsigned long long acc2[16];
    #pragma unroll
    for (int x = 0; x < 16; x++) acc2[x] = 0ull;

    for (int ci2 = 0; ci2 < 64; ci2++) {
        unsigned long long wv[9];
        #pragma unroll
        for (int t9 = 0; t9 < 9; t9++)
            wv[t9] = *reinterpret_cast<const unsigned long long*>(
                         wbase + ((size_t)(t9*64 + ci2)*256 + co*2));
        #pragma unroll
        for (int ky = 0; ky < 3; ky++) {
            unsigned long long r2[18];
            #pragma unroll
            for (int xi = 0; xi < 18; xi++)
                r2[xi] = *reinterpret_cast<const unsigned long long*>(&s_in[ky][xi][ci2*2]);
            #pragma unroll
            for (int kx = 0; kx < 3; kx++) {
                unsigned long long w = wv[ky*3 + kx];
                #pragma unroll
                for (int x = 0; x < 16; x++)
                    ffma2_ip(acc2[x], w, r2[x+kx]);
            }
        }
    }

    float bv = bias[co];
    float local = 0.f;
    #pragma unroll
    for (int x = 0; x < 16; x++) {
        float lo, hi;
        f2_unpack(acc2[x], lo, hi);
        float hval = s_in[1][x+1][co];
        float h2 = 0.5f*hval + 0.5f*((lo + hi) + bv);
        int idx = ((b*16+y)*16+x)*128 + co;
        float fh = g_fhat[idx] + h2;
        g_fhat[idx]  = fh;
        g_frest[idx] -= h2;
        float d = fh - g_f0[idx];
        local += d*d;
    }
    #pragma unroll
    for (int m = 16; m > 0; m >>= 1) local += __shfl_xor_sync(0xffffffffu, local, m);
    __shared__ float ws[4];
    if ((co & 31) == 0) ws[co >> 5] = local;
    __syncthreads();
    if (co == 0) atomicAdd(&g_sse[si], ws[0]+ws[1]+ws[2]+ws[3]);
}

__global__ void k_final(float* __restrict__ out) {
    int i = blockIdx.x*256 + threadIdx.x;
    int b  = i >> 15;
    int c  = (i >> 8) & 127;
    int yx = i & 255;
    out[i] = g_fhat[((((b << 8) | yx) << 7) | c)];
    if (i == 0) {
        float L = 0.f;
        for (int s = 0; s < 5; s++) L += 1.25f * (g_sse[s] / (float)NELEM);
        out[NELEM] = L / 5.f;
    }
}

// ---------------- launch ----------------
extern "C" void kernel_launch(void* const* d_in, const int* in_sizes, int n_in,
                              void* d_out, int out_size) {
    const float* cand0 = nullptr; const float* cand1 = nullptr;
    const float* pw = nullptr;    const float* pb = nullptr;
    for (int i = 0; i < n_in; i++) {
        int s = in_sizes[i];
        const float* p = (const float*)d_in[i];
        if      (s == 4*NCh*NCh*9) pw = p;
        else if (s == 4*NCh)       pb = p;
        else if (!cand0)           cand0 = p;
        else                       cand1 = p;
    }
    float* out = (float*)d_out;

    cudaFuncSetAttribute(k_mma, cudaFuncAttributeMaxDynamicSharedMemorySize, GEMM_SMEM);

    k_detect<<<1, 256>>>(cand0);
    k_init_all<<<10497, 256>>>(cand0, cand1, pw);

    const int pns[5]  = {1, 2, 4, 8, 16};
    const int kphi[5] = {0, 1, 2, 2, 3};
    const int vspl[5] = {64, 64, 32, 8, 2};

    for (int si = 0; si < 5; si++) {
        int pn = pns[si];
        int N  = NB * pn * pn;
        int use_frest = (pn == 16);
        int rowTiles = (N + 127) / 128;
        int vsplit   = vspl[si];
        int T = NV / (vsplit * 128);
        if (!use_frest) k_pool<<<N, 128>>>(pn);
        k_mma<<<dim3(rowTiles, vsplit), 512, GEMM_SMEM>>>(N, T, vsplit, use_frest);
        k_merge<<<(N + 255)/256, 256>>>(N, vsplit, use_frest);
        k_exact<<<128, 256>>>(cand0, cand1, use_frest);
        k_upsample<<<NPOS, 128>>>(cand0, cand1, pn, si);
        k_conv<<<dim3(16, NB), 128>>>(pb + kphi[si]*NCh, kphi[si], si);
    }
    k_final<<<4096, 256>>>(out);
}

// round 12
// speedup vs baseline: 1.7032x; 1.7032x over previous
#include <cuda_runtime.h>
#include <cuda_bf16.h>
#include <cstdint>

#define NB 32
#define NCh 128
#define NHW 16
#define NV 8192
#define NELEM (NB*NCh*NHW*NHW)   // 1048576
#define NPOS  (NB*NHW*NHW)       // 8192
// k_mma smem: [0,1024) hesq x2 | [1024,9216) merge buf | [16384,+64K) A | [81920,+32K)x2 B
#define GEMM_SMEM 147456
// k_exact2 smem: Es2 (64x65 ull) + As (64x132 f32)
#define EX_SMEM (64*65*8 + 64*132*4)

// ---------------- persistent device scratch ----------------
__device__ float g_frest[NELEM];              // NHWC (also pn=16 query matrix)
__device__ float g_fhat[NELEM];
__device__ float g_f0[NELEM];
__device__ float g_rest[NPOS*NCh];            // [N][128] pooled queries
__device__ float g_h[NELEM];
__device__ float g_half_esq[NV];
__device__ __nv_bfloat16 gB[NV*128];          // codebook hi-part
__device__ float g_t1s[NPOS*64];  __device__ int g_t1i[NPOS*64];
__device__ float g_t2s[NPOS*64];  __device__ int g_t2i[NPOS*64];
__device__ int   g_idx[NPOS];
__device__ int   g_flagcnt;
__device__ int   g_flaglist[NPOS];
__device__ unsigned long long g_bestx[NPOS];  // packed exact-rescan winners (per flag slot)
__device__ float g_wT2[4*9*64*256];           // conv weights [k][tap][ci2][co*2+p]
__device__ float g_Wall[5*16*16];
__device__ float g_sse[8];
__device__ int   g_swap;

// ---------------- f32x2 helpers ----------------
__device__ __forceinline__ unsigned long long f2_pack(float x, float y) {
    unsigned long long r;
    asm("mov.b64 %0, {%1, %2};" : "=l"(r) : "f"(x), "f"(y));
    return r;
}
__device__ __forceinline__ void f2_unpack(unsigned long long v, float& x, float& y) {
    asm("mov.b64 {%0, %1}, %2;" : "=f"(x), "=f"(y) : "l"(v));
}
__device__ __forceinline__ void ffma2_ip(unsigned long long& c,
                                         unsigned long long a, unsigned long long b) {
    asm("fma.rn.f32x2 %0, %1, %2, %0;" : "+l"(c) : "l"(a), "l"(b));
}
__device__ __forceinline__ unsigned long long pack_key(float sc, int col) {
    unsigned u = __float_as_uint(sc);
    u = (u & 0x80000000u) ? ~u : (u | 0x80000000u);   // monotone fp order
    return ((unsigned long long)u << 32) | (unsigned)(~col);  // ties -> smaller idx
}

// ---------------- mma / cp.async helpers ----------------
__device__ __forceinline__ uint32_t smem_u32(const void* p) {
    uint32_t a;
    asm("{ .reg .u64 t; cvta.to.shared.u64 t, %1; cvt.u32.u64 %0, t; }" : "=r"(a) : "l"(p));
    return a;
}
__device__ __forceinline__ void ldsm_x4(uint32_t& r0, uint32_t& r1, uint32_t& r2,
                                        uint32_t& r3, uint32_t addr) {
    asm volatile("ldmatrix.sync.aligned.m8n8.x4.shared.b16 {%0,%1,%2,%3}, [%4];"
        : "=r"(r0), "=r"(r1), "=r"(r2), "=r"(r3) : "r"(addr));
}
__device__ __forceinline__ void mma16816(float* d, const uint32_t* a, const uint32_t* b) {
    asm volatile("mma.sync.aligned.m16n8k16.row.col.f32.bf16.bf16.f32 "
        "{%0,%1,%2,%3}, {%4,%5,%6,%7}, {%8,%9}, {%0,%1,%2,%3};"
        : "+f"(d[0]), "+f"(d[1]), "+f"(d[2]), "+f"(d[3])
        : "r"(a[0]), "r"(a[1]), "r"(a[2]), "r"(a[3]), "r"(b[0]), "r"(b[1]));
}
__device__ __forceinline__ void cp16(uint32_t dst, const void* src) {
    asm volatile("cp.async.cg.shared.global [%0], [%1], 16;" :: "r"(dst), "l"(src));
}
__device__ __forceinline__ void cp_commit() {
    asm volatile("cp.async.commit_group;" ::: "memory");
}
template<int Nn> __device__ __forceinline__ void cp_wait() {
    asm volatile("cp.async.wait_group %0;" :: "n"(Nn) : "memory");
}
__device__ __forceinline__ void top2_merge(float& s1, int& i1, float& s2, int& i2,
                                           float os1, int oi1, float os2, int oi2) {
    if (os1 > s1 || (os1 == s1 && oi1 < i1)) {
        float ns2; int ni2;
        if (s1 > os2 || (s1 == os2 && i1 < oi2)) { ns2 = s1; ni2 = i1; }
        else { ns2 = os2; ni2 = oi2; }
        s1 = os1; i1 = oi1; s2 = ns2; i2 = ni2;
    } else {
        if (os1 > s2 || (os1 == s2 && oi1 < i2)) { s2 = os1; i2 = oi1; }
    }
}

// prefetch one B tile (128 codes x 128 bf16 = 32KB, 256B/row) + hesq via cp.async
__device__ __forceinline__ void prefetch_tile(uint32_t B_u, uint32_t sb, int bsel,
                                              int v0, int tid) {
    uint32_t Bb = B_u + (uint32_t)bsel*32768u;
    #pragma unroll
    for (int q = 0; q < 4; q++) {
        int idx  = q*512 + tid;
        int code = idx >> 4, c = idx & 15;
        cp16(Bb + (uint32_t)(code*256 + ((c ^ (code & 7)) << 4)),
             gB + (size_t)(v0 + code)*128 + c*8);
    }
    if (tid < 32) cp16(sb + (uint32_t)(bsel*512 + tid*16), g_half_esq + v0 + tid*4);
    cp_commit();
}

// ---------------- input disambiguation ----------------
__global__ void k_detect(const float* __restrict__ a) {
    __shared__ float red[256];
    int t = threadIdx.x;
    float s = 0.f;
    #pragma unroll 4
    for (int k = 0; k < 64; k++) { float x = a[t + 256*k]; s += x*x; }
    red[t] = s; __syncthreads();
    for (int m = 128; m > 0; m >>= 1) { if (t < m) red[t] += red[t+m]; __syncthreads(); }
    if (t == 0) g_swap = (red[0] > 0.5f * 16384.f) ? 0 : 1;
}

__device__ __forceinline__ double keys_cubic(double x) {
    x = fabs(x);
    if (x < 1.0) return ((1.5*x - 2.5)*x)*x + 1.0;
    if (x < 2.0) return ((-0.5*x + 2.5)*x - 4.0)*x + 2.0;
    return 0.0;
}

// ---------------- merged init (grid-partitioned) ----------------
__global__ void k_init_all(const float* __restrict__ a, const float* __restrict__ b,
                           const float* __restrict__ phi_w) {
    int blk = blockIdx.x;
    int t = threadIdx.x;
    if (blk < 4096) {
        const float* f = g_swap ? b : a;
        int i = blk*256 + t;
        if (i < 8) g_sse[i] = 0.f;
        int bb = i >> 15;
        int c  = (i >> 8) & 127;
        int yx = i & 255;
        int nh = ((((bb << 8) | yx) << 7) | c);
        float v = f[i];
        g_frest[nh] = v;
        g_f0[nh]    = v;
        g_fhat[nh]  = 0.f;
    } else if (blk < 8192) {
        const float* emb = g_swap ? a : b;
        int v0 = (blk - 4096)*2;
        int v = v0 + (t >> 7);
        int c = t & 127;
        float x = emb[v*NCh + c];
        gB[(size_t)v*128 + c] = __float2bfloat16(x);
        float s = x*x;
        #pragma unroll
        for (int m = 16; m > 0; m >>= 1) s += __shfl_xor_sync(0xffffffffu, s, m);
        __shared__ float ws[8];
        if ((t & 31) == 0) ws[t >> 5] = s;
        __syncthreads();
        if (t == 0)   g_half_esq[v0]   = 0.5f*(ws[0]+ws[1]+ws[2]+ws[3]);
        if (t == 128) g_half_esq[v0+1] = 0.5f*(ws[4]+ws[5]+ws[6]+ws[7]);
    } else if (blk < 10496) {
        int o = (blk - 8192)*256 + t;
        int co2 = o & 255;
        int p  = co2 & 1;
        int co = co2 >> 1;
        int r  = o >> 8;
        int ci2 = r & 63; r >>= 6;
        int t9 = r % 9;
        int k  = r / 9;
        int ky = t9 / 3, kx = t9 % 3;
        int ci = ci2*2 + p;
        g_wT2[o] = phi_w[(((k*NCh + co)*NCh + ci)*3 + ky)*3 + kx];
    } else {
        if (t >= 80) return;
        const int pns[5] = {1,2,4,8,16};
        int si = t >> 4, i = t & 15;
        int pn = pns[si];
        double sample = (i + 0.5) * (double)pn / 16.0 - 0.5;
        double w[16]; double tot = 0.0;
        for (int j = 0; j < 16; j++) w[j] = 0.0;
        for (int j = 0; j < pn; j++) { w[j] = keys_cubic(sample - (double)j); tot += w[j]; }
        for (int j = 0; j < 16; j++) g_Wall[(si*16 + i)*16 + j] = (float)(w[j] / tot);
    }
}

// ---------------- stage kernels ----------------
__global__ void k_pool(int pn) {
    int n = blockIdx.x;
    int c = threadIdx.x;
    int s = 16 / pn;
    int pp = pn*pn;
    int b   = n / pp;
    int rem = n - b*pp;
    int py = rem / pn, px = rem - py*pn;
    float acc = 0.f;
    int y0 = py*s, x0 = px*s;
    for (int dy = 0; dy < s; dy++)
        for (int dx = 0; dx < s; dx++)
            acc += g_frest[(((b*16 + y0+dy)*16) + (x0+dx))*128 + c];
    g_rest[n*128 + c] = acc / (float)(s*s);
}

// tensor-core NN: 128 rows x 128 codes/tile, K=256 (A=[hi|lo], B=hi wraps),
// cp.async double-buffered B, 512 threads (warps 4m x 4n, each 32x32).
__global__ __launch_bounds__(512, 1) void k_mma(int N, int T, int vsplit, int use_frest) {
    extern __shared__ char smem[];
    uint32_t sb = smem_u32(smem);
    float4* buf = (float4*)(smem + 1024);         // [128 rows][4 wn]
    uint32_t A_u = sb + 16384;
    uint32_t B_u = sb + 81920;
    const float* R = use_frest ? g_frest : g_rest;

    int tid = threadIdx.x;
    int wid = tid >> 5, lane = tid & 31;
    int wm = wid >> 2, wn = wid & 3;
    int rt = blockIdx.x, vslab = blockIdx.y;
    int r0 = rt * 128;
    if (rt == 0 && vslab == 0 && tid == 0) g_flagcnt = 0;

    int vbase = vslab * T * 128;
    prefetch_tile(B_u, sb, 0, vbase, tid);

    // ---- A' prep: 128 rows x 256 bf16 [hi(0..15) | lo(16..31)] chunks, XOR swizzle ----
    {
        int row = tid >> 2, q4 = tid & 3;
        int grow = r0 + row;
        bool valid = grow < N;
        const float4* rp = (const float4*)(R + (size_t)grow*128) + q4*8;
        int xm = row & 7;
        char* Arow = smem + 16384 + row*512;
        #pragma unroll
        for (int p = 0; p < 4; p++) {
            float4 va = valid ? rp[2*p]   : make_float4(0.f,0.f,0.f,0.f);
            float4 vb = valid ? rp[2*p+1] : make_float4(0.f,0.f,0.f,0.f);
            float xs[8] = {va.x,va.y,va.z,va.w,vb.x,vb.y,vb.z,vb.w};
            uint32_t hw[4], lw[4];
            #pragma unroll
            for (int j = 0; j < 4; j++) {
                __nv_bfloat16 h0 = __float2bfloat16(xs[2*j]);
                __nv_bfloat16 h1 = __float2bfloat16(xs[2*j+1]);
                float l0 = xs[2*j]   - __bfloat162float(h0);
                float l1 = xs[2*j+1] - __bfloat162float(h1);
                __nv_bfloat16 g0 = __float2bfloat16(l0);
                __nv_bfloat16 g1 = __float2bfloat16(l1);
                hw[j] = (uint32_t)__bfloat16_as_ushort(h0) |
                        ((uint32_t)__bfloat16_as_ushort(h1) << 16);
                lw[j] = (uint32_t)__bfloat16_as_ushort(g0) |
                        ((uint32_t)__bfloat16_as_ushort(g1) << 16);
            }
            int ch = q4*4 + p;
            int cl = 16 + q4*4 + p;
            *(uint4*)(Arow + ((ch ^ xm) << 4)) = make_uint4(hw[0],hw[1],hw[2],hw[3]);
            *(uint4*)(Arow + ((cl ^ xm) << 4)) = make_uint4(lw[0],lw[1],lw[2],lw[3]);
        }
    }

    float bs1[2][2], bs2[2][2]; int bi1[2][2], bi2[2][2];
    #pragma unroll
    for (int m = 0; m < 2; m++)
        #pragma unroll
        for (int h = 0; h < 2; h++) {
            bs1[m][h] = -3.4e38f; bs2[m][h] = -3.4e38f;
            bi1[m][h] = 0x7fffffff; bi2[m][h] = 0x7fffffff;
        }

    int a_off[2], a_x[2];
    #pragma unroll
    for (int m = 0; m < 2; m++) {
        int arow = wm*32 + m*16 + (lane & 15);
        a_off[m] = arow*512; a_x[m] = arow & 7;
    }
    int ahi = lane >> 4;
    int b_off[2], b_x[2];
    #pragma unroll
    for (int nb = 0; nb < 2; nb++) {
        int brow = wn*32 + nb*16 + ((lane >> 4) << 3) + (lane & 7);
        b_off[nb] = brow*256; b_x[nb] = brow & 7;
    }
    int bhi = (lane >> 3) & 1;

    for (int t = 0; t < T; t++) {
        if (t + 1 < T) prefetch_tile(B_u, sb, (t+1) & 1, vbase + (t+1)*128, tid);
        if (t + 1 < T) cp_wait<1>(); else cp_wait<0>();
        __syncthreads();

        uint32_t Bb = B_u + (uint32_t)((t & 1)*32768);
        const float* hs = (const float*)(smem + (t & 1)*512);
        int v0 = vbase + t*128;

        float acc[2][4][4];
        #pragma unroll
        for (int m = 0; m < 2; m++)
            #pragma unroll
            for (int n = 0; n < 4; n++)
                #pragma unroll
                for (int j = 0; j < 4; j++) acc[m][n][j] = 0.f;

        #pragma unroll 4
        for (int ks = 0; ks < 16; ks++) {
            uint32_t af[2][4];
            #pragma unroll
            for (int m = 0; m < 2; m++) {
                uint32_t addr = A_u + a_off[m] + (uint32_t)(((ks*2 + ahi) ^ a_x[m]) << 4);
                ldsm_x4(af[m][0], af[m][1], af[m][2], af[m][3], addr);
            }
            uint32_t bfr[2][4];
            #pragma unroll
            for (int nb = 0; nb < 2; nb++) {
                int chunk = (ks*2 + bhi) & 15;     // B wraps: lo ksteps reuse hi codebook
                uint32_t addr = Bb + b_off[nb] + (uint32_t)((chunk ^ b_x[nb]) << 4);
                ldsm_x4(bfr[nb][0], bfr[nb][1], bfr[nb][2], bfr[nb][3], addr);
            }
            #pragma unroll
            for (int m = 0; m < 2; m++)
                #pragma unroll
                for (int n = 0; n < 4; n++)
                    mma16816(acc[m][n], af[m], &bfr[n >> 1][(n & 1)*2]);
        }

        #pragma unroll
        for (int m = 0; m < 2; m++)
            #pragma unroll
            for (int h = 0; h < 2; h++) {
                float s1 = bs1[m][h], s2 = bs2[m][h];
                int   i1 = bi1[m][h], i2 = bi2[m][h];
                #pragma unroll
                for (int n = 0; n < 4; n++) {
                    int cc = wn*32 + n*8 + (lane & 3)*2;
                    #pragma unroll
                    for (int j = 0; j < 2; j++) {
                        float s = acc[m][n][h*2 + j] - hs[cc + j];
                        int code = v0 + cc + j;
                        if (s > s1) { s2 = s1; i2 = i1; s1 = s; i1 = code; }
                        else if (s > s2) { s2 = s; i2 = code; }
                    }
                }
                bs1[m][h] = s1; bs2[m][h] = s2; bi1[m][h] = i1; bi2[m][h] = i2;
            }
        __syncthreads();
    }

    // quad-lane merge (lanes with same lane>>2 cover same rows)
    #pragma unroll
    for (int m = 0; m < 2; m++)
        #pragma unroll
        for (int h = 0; h < 2; h++) {
            float s1 = bs1[m][h], s2 = bs2[m][h];
            int   i1 = bi1[m][h], i2 = bi2[m][h];
            #pragma unroll
            for (int d = 1; d <= 2; d <<= 1) {
                float os1 = __shfl_xor_sync(0xffffffffu, s1, d);
                int   oi1 = __shfl_xor_sync(0xffffffffu, i1, d);
                float os2 = __shfl_xor_sync(0xffffffffu, s2, d);
                int   oi2 = __shfl_xor_sync(0xffffffffu, i2, d);
                top2_merge(s1, i1, s2, i2, os1, oi1, os2, oi2);
            }
            if ((lane & 3) == 0) {
                int row = wm*32 + m*16 + h*8 + (lane >> 2);
                buf[row*4 + wn] = make_float4(s1, __int_as_float(i1),
                                              s2, __int_as_float(i2));
            }
        }
    __syncthreads();

    if (tid < 128) {
        float4 p = buf[tid*4];
        float s1 = p.x, s2 = p.z; int i1 = __float_as_int(p.y), i2 = __float_as_int(p.w);
        #pragma unroll
        for (int w = 1; w < 4; w++) {
            float4 q = buf[tid*4 + w];
            top2_merge(s1, i1, s2, i2, q.x, __float_as_int(q.y), q.z, __float_as_int(q.w));
        }
        int grow = r0 + tid;
        if (grow < N) {
            int o = grow*vsplit + vslab;
            g_t1s[o] = s1; g_t1i[o] = i1;
            g_t2s[o] = s2; g_t2i[o] = i2;
        }
    }
}

// merge per-slab top-2; flag ambiguous rows (and zero their exact-winner slot)
__global__ void k_merge(int N, int vsplit, int use_frest) {
    int r = blockIdx.x*256 + threadIdx.x;
    if (r >= N) return;
    int o0 = r*vsplit;
    float s1 = g_t1s[o0], s2 = g_t2s[o0];
    int   i1 = g_t1i[o0], i2 = g_t2i[o0];
    for (int sl = 1; sl < vsplit; sl++) {
        int o = o0 + sl;
        top2_merge(s1, i1, s2, i2, g_t1s[o], g_t1i[o], g_t2s[o], g_t2i[o]);
    }
    const float* R = use_frest ? g_frest : g_rest;
    const float4* rp = (const float4*)(R + (size_t)r*128);
    float nr = 0.f;
    #pragma unroll 8
    for (int q = 0; q < 32; q++) {
        float4 v = rp[q];
        nr += v.x*v.x + v.y*v.y + v.z*v.z + v.w*v.w;
    }
    float eps = 4e-3f * sqrtf(nr) + 1e-3f;
    g_idx[r] = i1;
    if (s1 - s2 <= eps) {
        int p = atomicAdd(&g_flagcnt, 1);
        g_flaglist[p] = r;
        g_bestx[p] = 0ull;
    }
}

// batched exact fp32 rescan of flagged rows: 64-row tiles x split-V=16,
// FFMA2 GEMM (identical math/ordering to the proven R6 k_nn), atomicMax merge.
__global__ __launch_bounds__(256) void k_exact2(const float* __restrict__ a_,
                                                const float* __restrict__ b_,
                                                int use_frest) {
    int nflag = g_flagcnt;
    int r0 = blockIdx.x * 64;
    if (r0 >= nflag) return;
    const float* emb = g_swap ? a_ : b_;
    const float* R = use_frest ? g_frest : g_rest;
    extern __shared__ unsigned long long smu[];
    unsigned long long* Es2 = smu;                    // [64 k2][65] float2 per code
    float* As = (float*)(smu + 64*65);                // [64 rows][132] floats
    int vbase = blockIdx.y * 512;
    int t = threadIdx.x;

    #pragma unroll
    for (int q = 0; q < 8; q++) {
        int idx4 = t + q*256;
        int row = idx4 >> 5;
        int k4  = idx4 & 31;
        float4 v = make_float4(0.f,0.f,0.f,0.f);
        int p = r0 + row;
        if (p < nflag)
            v = reinterpret_cast<const float4*>(R + (size_t)g_flaglist[p]*128)[k4];
        *reinterpret_cast<float4*>(&As[row*132 + k4*4]) = v;
    }

    int tm = t >> 4, tv = t & 15;
    unsigned long long bkey[4];
    #pragma unroll
    for (int i = 0; i < 4; i++) bkey[i] = 0ull;

    for (int it = 0; it < 8; it++) {
        int v0 = vbase + it*64;
        __syncthreads();
        #pragma unroll
        for (int q = 0; q < 8; q++) {
            int idx4 = t + q*256;
            int code = idx4 & 63;
            int kc   = idx4 >> 6;
            float4 v = reinterpret_cast<const float4*>(emb + (size_t)(v0+code)*128)[kc];
            Es2[(2*kc  )*65 + code] = f2_pack(v.x, v.y);
            Es2[(2*kc+1)*65 + code] = f2_pack(v.z, v.w);
        }
        __syncthreads();

        unsigned long long acc[4][4];
        #pragma unroll
        for (int i = 0; i < 4; i++)
            #pragma unroll
            for (int j = 0; j < 4; j++) acc[i][j] = 0ull;

        #pragma unroll 8
        for (int k2 = 0; k2 < 64; k2++) {
            unsigned long long av[4], e[4];
            #pragma unroll
            for (int i = 0; i < 4; i++)
                av[i] = *reinterpret_cast<const unsigned long long*>(&As[(tm*4+i)*132 + k2*2]);
            #pragma unroll
            for (int j = 0; j < 4; j++)
                e[j] = Es2[k2*65 + (tv + 16*j)];
            #pragma unroll
            for (int i = 0; i < 4; i++)
                #pragma unroll
                for (int j = 0; j < 4; j++)
                    ffma2_ip(acc[i][j], av[i], e[j]);
        }

        #pragma unroll
        for (int j = 0; j < 4; j++) {
            int col = v0 + tv + 16*j;
            float hsq = g_half_esq[col];
            #pragma unroll
            for (int i = 0; i < 4; i++) {
                float lo, hi;
                f2_unpack(acc[i][j], lo, hi);
                unsigned long long key = pack_key((lo + hi) - hsq, col);
                if (key > bkey[i]) bkey[i] = key;
            }
        }
    }

    #pragma unroll
    for (int m = 8; m >= 1; m >>= 1)
        #pragma unroll
        for (int i = 0; i < 4; i++) {
            unsigned long long o = __shfl_xor_sync(0xffffffffu, bkey[i], m);
            if (o > bkey[i]) bkey[i] = o;
        }
    if (tv == 0) {
        #pragma unroll
        for (int i = 0; i < 4; i++) {
            int p = r0 + tm*4 + i;
            if (p < nflag) atomicMax(&g_bestx[p], bkey[i]);
        }
    }
}

// writeback exact winners to g_idx
__global__ void k_wb() {
    int p = blockIdx.x*256 + threadIdx.x;
    if (p < g_flagcnt) g_idx[g_flaglist[p]] = (int)(~(unsigned)g_bestx[p]);
}

// gather + separable-cubic upsample (pn=16 -> pure gather)
__global__ void k_upsample(const float* __restrict__ a_, const float* __restrict__ b_,
                           int pn, int si) {
    const float* emb = g_swap ? a_ : b_;
    int blk = blockIdx.x;
    int c = threadIdx.x;
    if (pn == 16) {
        g_h[(size_t)blk*128 + c] = emb[(size_t)g_idx[blk]*128 + c];
        return;
    }
    int b = blk >> 8;
    int Y = (blk >> 4) & 15;
    int X = blk & 15;
    const float* Wm = g_Wall + si*256;
    float acc = 0.f;
    for (int py = 0; py < pn; py++) {
        float wy = Wm[Y*16 + py];
        if (wy == 0.f) continue;
        for (int px = 0; px < pn; px++) {
            float wx = Wm[X*16 + px];
            if (wx == 0.f) continue;
            int n = (b*pn + py)*pn + px;
            acc += (wy*wx) * emb[(size_t)g_idx[n]*128 + c];
        }
    }
    g_h[(size_t)blk*128 + c] = acc;
}

// Phi + fused residual update + loss (validated f32x2 path)
__global__ __launch_bounds__(128) void k_conv(const float* __restrict__ bias, int kphi, int si) {
    __shared__ float s_in[3][18][128];
    int y  = blockIdx.x;
    int b  = blockIdx.y;
    int co = threadIdx.x;
    const float* wbase = g_wT2 + (size_t)kphi*(9*64*256);

    #pragma unroll
    for (int ky = 0; ky < 3; ky++) {
        int yy = y + ky - 1;
        #pragma unroll
        for (int xi = 0; xi < 18; xi++) {
            int xx = xi - 1;
            float v = 0.f;
            if (yy >= 0 && yy < 16 && xx >= 0 && xx < 16)
                v = g_h[((b*16+yy)*16+xx)*128 + co];
            s_in[ky][xi][co] = v;
        }
    }
    __syncthreads();

    unsigned long long acc2[16];
    #pragma unroll
    for (int x = 0; x < 16; x++) acc2[x] = 0ull;

    for (int ci2 = 0; ci2 < 64; ci2++) {
        unsigned long long wv[9];
        #pragma unroll
        for (int t9 = 0; t9 < 9; t9++)
            wv[t9] = *reinterpret_cast<const unsigned long long*>(
                         wbase + ((size_t)(t9*64 + ci2)*256 + co*2));
        #pragma unroll
        for (int ky = 0; ky < 3; ky++) {
            unsigned long long r2[18];
            #pragma unroll
            for (int xi = 0; xi < 18; xi++)
                r2[xi] = *reinterpret_cast<const unsigned long long*>(&s_in[ky][xi][ci2*2]);
            #pragma unroll
            for (int kx = 0; kx < 3; kx++) {
                unsigned long long w = wv[ky*3 + kx];
                #pragma unroll
                for (int x = 0; x < 16; x++)
                    ffma2_ip(acc2[x], w, r2[x+kx]);
            }
        }
    }

    float bv = bias[co];
    float local = 0.f;
    #pragma unroll
    for (int x = 0; x < 16; x++) {
        float lo, hi;
        f2_unpack(acc2[x], lo, hi);
        float hval = s_in[1][x+1][co];
        float h2 = 0.5f*hval + 0.5f*((lo + hi) + bv);
        int idx = ((b*16+y)*16+x)*128 + co;
        float fh = g_fhat[idx] + h2;
        g_fhat[idx]  = fh;
        g_frest[idx] -= h2;
        float d = fh - g_f0[idx];
        local += d*d;
    }
    #pragma unroll
    for (int m = 16; m > 0; m >>= 1) local += __shfl_xor_sync(0xffffffffu, local, m);
    __shared__ float ws[4];
    if ((co & 31) == 0) ws[co >> 5] = local;
    __syncthreads();
    if (co == 0) atomicAdd(&g_sse[si], ws[0]+ws[1]+ws[2]+ws[3]);
}

__global__ void k_final(float* __restrict__ out) {
    int i = blockIdx.x*256 + threadIdx.x;
    int b  = i >> 15;
    int c  = (i >> 8) & 127;
    int yx = i & 255;
    out[i] = g_fhat[((((b << 8) | yx) << 7) | c)];
    if (i == 0) {
        float L = 0.f;
        for (int s = 0; s < 5; s++) L += 1.25f * (g_sse[s] / (float)NELEM);
        out[NELEM] = L / 5.f;
    }
}

// ---------------- launch ----------------
extern "C" void kernel_launch(void* const* d_in, const int* in_sizes, int n_in,
                              void* d_out, int out_size) {
    const float* cand0 = nullptr; const float* cand1 = nullptr;
    const float* pw = nullptr;    const float* pb = nullptr;
    for (int i = 0; i < n_in; i++) {
        int s = in_sizes[i];
        const float* p = (const float*)d_in[i];
        if      (s == 4*NCh*NCh*9) pw = p;
        else if (s == 4*NCh)       pb = p;
        else if (!cand0)           cand0 = p;
        else                       cand1 = p;
    }
    float* out = (float*)d_out;

    cudaFuncSetAttribute(k_mma, cudaFuncAttributeMaxDynamicSharedMemorySize, GEMM_SMEM);
    cudaFuncSetAttribute(k_exact2, cudaFuncAttributeMaxDynamicSharedMemorySize, EX_SMEM);

    k_detect<<<1, 256>>>(cand0);
    k_init_all<<<10497, 256>>>(cand0, cand1, pw);

    const int pns[5]  = {1, 2, 4, 8, 16};
    const int kphi[5] = {0, 1, 2, 2, 3};
    const int vspl[5] = {64, 64, 32, 8, 2};

    for (int si = 0; si < 5; si++) {
        int pn = pns[si];
        int N  = NB * pn * pn;
        int use_frest = (pn == 16);
        int rowTiles = (N + 127) / 128;
        int vsplit   = vspl[si];
        int T = NV / (vsplit * 128);
        if (!use_frest) k_pool<<<N, 128>>>(pn);
        k_mma<<<dim3(rowTiles, vsplit), 512, GEMM_SMEM>>>(N, T, vsplit, use_frest);
        k_merge<<<(N + 255)/256, 256>>>(N, vsplit, use_frest);
        k_exact2<<<dim3((N + 63)/64, 16), 256, EX_SMEM>>>(cand0, cand1, use_frest);
        k_wb<<<(N + 255)/256, 256>>>();
        k_upsample<<<NPOS, 128>>>(cand0, cand1, pn, si);
        k_conv<<<dim3(16, NB), 128>>>(pb + kphi[si]*NCh, kphi[si], si);
    }
    k_final<<<4096, 256>>>(out);
}